// round 12
// baseline (speedup 1.0000x reference)
#include <cuda_runtime.h>
#include <math.h>

#define BN 32     // B*C images
#define HH 256
#define WW 256
#define TILE 16   // output rows per block
#define HALO 2    // shared halo rows each side (window r<=2 exact)
#define SROWS (TILE + 2*HALO)   // 20
#define FG_INF 1e6f
#define BIGF   3.0e38f          // padding: r2 + BIGF never wins, no overflow

__device__ __forceinline__ float sqrt_approx(float x) {
    float y;
    asm("sqrt.approx.f32 %0, %1;" : "=f"(y) : "f"(x));
    return y;
}

// exact per-pixel row distance recompute from x (cold path, ~never taken)
__device__ __forceinline__ float row_g_global(const float* __restrict__ xrow, int j) {
    if (xrow[j] == 0.0f) return 0.0f;
    int dl = 1 << 30, dr = 1 << 30;
    for (int t = j - 1; t >= 0; --t) if (xrow[t] == 0.0f) { dl = j - t; break; }
    for (int t = j + 1; t < WW; ++t) if (xrow[t] == 0.0f) { dr = t - j; break; }
    int d = min(dl, dr);
    if (d >= (1 << 30)) return FG_INF + fminf((float)(j + 1), (float)(WW - j));
    return (float)d;
}

__global__ void __launch_bounds__(512, 3)
edt_fused(const float* __restrict__ x, float* __restrict__ out) {
    __shared__ float g2s[SROWS][WW];   // 20 KB; sign bit = "input was NaN"

    const int n  = blockIdx.y;                 // image
    const int i0 = blockIdx.x * TILE;          // first output row
    const int rowbase = i0 - HALO;             // global row of shared row 0
    const int b    = threadIdx.x & 31;         // lane
    const int wrp  = threadIdx.x >> 5;         // 0..15

    // --- Phase 1: row distances (warp-per-row, branch-free funnel windows) ---
    #pragma unroll
    for (int pass = 0; pass < 2; ++pass) {
        const int lr = wrp + pass * 16;        // local shared row
        if (lr >= SROWS) break;                // warp-uniform
        const int gr = rowbase + lr;           // global row
        if (gr < 0 || gr >= HH) {
            #pragma unroll
            for (int k = 0; k < 8; ++k) g2s[lr][b + 32 * k] = BIGF;
            continue;
        }
        const float* __restrict__ xr = x + (n * HH + gr) * WW;

        unsigned mm[10];                       // bg mask words, zero-padded ends
        unsigned nn8 = 0u;                     // bit k = isnan(pixel b+32k)
        mm[0] = 0u; mm[9] = 0u;
        #pragma unroll
        for (int k = 0; k < 8; ++k) {
            const float xv = xr[b + 32 * k];
            mm[k + 1] = __ballot_sync(0xFFFFFFFFu, xv == 0.0f);  // NaN -> fg
            nn8 |= ((unsigned)isnan(xv)) << k;
        }

        unsigned cold = 0u;
        #pragma unroll
        for (int k = 0; k < 8; ++k) {
            // self-inclusive windows: R bit t = pixel j+t, L bit (31-t) = pixel j-t
            const unsigned R = __funnelshift_rc(mm[k + 1], mm[k + 2], b);
            const unsigned L = __funnelshift_lc(mm[k], mm[k + 1], 31 - b);
            const int dr = R ? (__ffs(R) - 1) : 1000;
            const int dl = L ? __clz(L) : 1000;
            const int d = min(dr, dl);
            cold |= ((unsigned)(d >= 1000)) << k;
            float s2 = (float)(d * d);
            // inject NaN flag into sign bit (fg => d>=1, bg never NaN)
            s2 = __uint_as_float(__float_as_uint(s2) |
                                 (((nn8 >> k) & 1u) << 31));
            g2s[lr][b + 32 * k] = s2;
        }
        if (__any_sync(0xFFFFFFFFu, cold != 0u)) {   // ~never taken
            #pragma unroll 1
            for (int k = 0; k < 8; ++k) if ((cold >> k) & 1u) {
                const int j = b + 32 * k;
                const float g = row_g_global(xr, j);
                float s2 = g * g;
                s2 = __uint_as_float(__float_as_uint(s2) |
                                     (((nn8 >> k) & 1u) << 31));
                g2s[lr][j] = s2;
            }
        }
    }
    __syncthreads();

    // --- Phase 2: column lower-envelope, branch-free r<=2 window, ballot tail ---
    const int j   = threadIdx.x & (WW - 1);    // column
    const int lo0 = (threadIdx.x >> 8) * 8;    // 0 or 8: first of 8 output rows

    float v[12];                               // shared rows lo0 .. lo0+11
    #pragma unroll
    for (int t = 0; t < 12; ++t)
        v[t] = g2s[lo0 + t][j];

    unsigned need = 0u;
    #pragma unroll
    for (int p = 0; p < 8; ++p) {
        const int c = 2 + p;                   // center: shared row lo0+p+2
        const bool nanp = signbit(v[c]);
        float best = fabsf(v[c]);
        best = fminf(best, 1.0f + fabsf(v[c - 1]));
        best = fminf(best, 1.0f + fabsf(v[c + 1]));
        best = fminf(best, 4.0f + fabsf(v[c - 2]));
        best = fminf(best, 4.0f + fabsf(v[c + 2]));
        need |= ((unsigned)(best > 9.0f)) << p;
        const float d = sqrt_approx(best);
        out[(n * HH + i0 + lo0 + p) * WW + j] =
            nanp ? __int_as_float(0x7FC00000) : d;
    }

    // exact tail, warp-uniform guard, ~never taken (needs d^2 > 9)
    if (__any_sync(0xFFFFFFFFu, need != 0u)) {
        #pragma unroll 1
        for (int p = 0; p < 8; ++p) if ((need >> p) & 1u) {
            const int s = HALO + lo0 + p;      // this pixel's shared row
            const int i = i0 + lo0 + p;        // global row
            const bool nanp = signbit(g2s[s][j]);
            float best = fabsf(g2s[s][j]);
            best = fminf(best, 1.0f + fabsf(g2s[s - 1][j]));
            best = fminf(best, 1.0f + fabsf(g2s[s + 1][j]));
            best = fminf(best, 4.0f + fabsf(g2s[s - 2][j]));
            best = fminf(best, 4.0f + fabsf(g2s[s + 2][j]));
            // exact global recompute for r >= 3 (cold)
            for (int r = 3; r < HH; ++r) {
                const float r2 = (float)(r * r);
                if (r2 >= best) break;
                const int up = i - r, dn = i + r;
                if (up >= 0) {
                    const float g = row_g_global(x + (n * HH + up) * WW, j);
                    best = fminf(best, r2 + g * g);
                }
                if (dn < HH) {
                    const float g = row_g_global(x + (n * HH + dn) * WW, j);
                    best = fminf(best, r2 + g * g);
                }
            }
            out[(n * HH + i) * WW + j] =
                nanp ? __int_as_float(0x7FC00000) : sqrt_approx(best);
        }
    }
}

extern "C" void kernel_launch(void* const* d_in, const int* in_sizes, int n_in,
                              void* d_out, int out_size) {
    const float* x = (const float*)d_in[0];
    float* out = (float*)d_out;
    edt_fused<<<dim3(HH / TILE, BN), 512>>>(x, out);
}

// round 13
// speedup vs baseline: 1.0269x; 1.0269x over previous
#include <cuda_runtime.h>
#include <math.h>

#define BN 32     // B*C images
#define HH 256
#define WW 256
#define TILE 16   // output rows per block
#define HALO 2    // shared halo rows each side (window r<=2 exact)
#define SROWS (TILE + 2*HALO)   // 20
#define FG_INF 1e6f
#define BIGF   3.0e38f          // padding: r2 + BIGF never wins, no overflow

__device__ __forceinline__ float sqrt_approx(float x) {
    float y;                    // x < 0 -> NaN (used for NaN passthrough)
    asm("sqrt.approx.f32 %0, %1;" : "=f"(y) : "f"(x));
    return y;
}

// exact per-pixel row distance recompute from x (cold path, ~never taken)
__device__ __forceinline__ float row_g_global(const float* __restrict__ xrow, int j) {
    if (xrow[j] == 0.0f) return 0.0f;
    int dl = 1 << 30, dr = 1 << 30;
    for (int t = j - 1; t >= 0; --t) if (xrow[t] == 0.0f) { dl = j - t; break; }
    for (int t = j + 1; t < WW; ++t) if (xrow[t] == 0.0f) { dr = t - j; break; }
    int d = min(dl, dr);
    if (d >= (1 << 30)) return FG_INF + fminf((float)(j + 1), (float)(WW - j));
    return (float)d;
}

__global__ void __launch_bounds__(512, 3)
edt_fused(const float* __restrict__ x, float* __restrict__ out) {
    __shared__ float g2s[SROWS][WW];   // 20 KB; sign bit = "input was NaN"

    const int n  = blockIdx.y;                 // image
    const int i0 = blockIdx.x * TILE;          // first output row
    const int rowbase = i0 - HALO;             // global row of shared row 0
    const int b    = threadIdx.x & 31;         // lane
    const int wrp  = threadIdx.x >> 5;         // 0..15

    // --- Phase 1: row distances (warp-per-row, merged brev|clz search) ---
    #pragma unroll
    for (int pass = 0; pass < 2; ++pass) {
        const int lr = wrp + pass * 16;        // local shared row
        if (lr >= SROWS) break;                // warp-uniform
        const int gr = rowbase + lr;           // global row
        if (gr < 0 || gr >= HH) {
            #pragma unroll
            for (int k = 0; k < 8; ++k) g2s[lr][b + 32 * k] = BIGF;
            continue;
        }
        const float* __restrict__ xr = x + (n * HH + gr) * WW;

        unsigned mm[10];                       // bg mask words, zero-padded ends
        unsigned nn8 = 0u;                     // bit k = isnan(pixel b+32k)
        mm[0] = 0u; mm[9] = 0u;
        #pragma unroll
        for (int k = 0; k < 8; ++k) {
            const float xv = xr[b + 32 * k];
            mm[k + 1] = __ballot_sync(0xFFFFFFFFu, xv == 0.0f);  // NaN -> fg
            nn8 |= ((unsigned)isnan(xv)) << k;
        }

        unsigned cold = 0u;
        #pragma unroll
        for (int k = 0; k < 8; ++k) {
            // self-inclusive windows: R bit t = pixel j+t ; L bit (31-t) = pixel j-t
            const unsigned R = __funnelshift_rc(mm[k + 1], mm[k + 2], b);
            const unsigned L = __funnelshift_lc(mm[k], mm[k + 1], 31 - b);
            // Urev bit (31-t) = bg at |distance| t (either side); clz = nearest d
            const unsigned Urev = __brev(R) | L;
            const int d = __clz(Urev);         // 32 if no bg within +-31 px
            cold |= ((unsigned)(d >= 32)) << k;
            const float fd = (float)d;
            float s2 = fd * fd;
            // inject NaN flag into sign bit (fg => d>=1, bg never NaN)
            s2 = __uint_as_float(__float_as_uint(s2) |
                                 (((nn8 >> k) & 1u) << 31));
            g2s[lr][b + 32 * k] = s2;
        }
        if (__any_sync(0xFFFFFFFFu, cold != 0u)) {   // ~never taken
            #pragma unroll 1
            for (int k = 0; k < 8; ++k) if ((cold >> k) & 1u) {
                const int j = b + 32 * k;
                const float g = row_g_global(xr, j);
                float s2 = g * g;
                s2 = __uint_as_float(__float_as_uint(s2) |
                                     (((nn8 >> k) & 1u) << 31));
                g2s[lr][j] = s2;
            }
        }
    }
    __syncthreads();

    // --- Phase 2: column-pair lower-envelope, r<=2 window, ballot tail ---
    // thread owns columns {2cp, 2cp+1} and 4 output rows.
    const int cp = threadIdx.x & 127;          // column pair index
    const int q  = threadIdx.x >> 7;           // 0..3 row chunk
    const int lo0 = q * 4;                     // first local output row

    float2 v[8];                               // shared rows lo0 .. lo0+7
    #pragma unroll
    for (int t = 0; t < 8; ++t)
        v[t] = *reinterpret_cast<const float2*>(&g2s[lo0 + t][2 * cp]);

    unsigned need = 0u;
    #pragma unroll
    for (int p = 0; p < 4; ++p) {
        const int c = 2 + p;                   // center index in v
        // keep center SIGNED: NaN-flagged centers are negative -> win the min
        // -> sqrt.approx(negative) = NaN output, no select needed.
        float bx = v[c].x;
        bx = fminf(bx, 1.0f + fabsf(v[c - 1].x));
        bx = fminf(bx, 1.0f + fabsf(v[c + 1].x));
        bx = fminf(bx, 4.0f + fabsf(v[c - 2].x));
        bx = fminf(bx, 4.0f + fabsf(v[c + 2].x));
        float by = v[c].y;
        by = fminf(by, 1.0f + fabsf(v[c - 1].y));
        by = fminf(by, 1.0f + fabsf(v[c + 1].y));
        by = fminf(by, 4.0f + fabsf(v[c - 2].y));
        by = fminf(by, 4.0f + fabsf(v[c + 2].y));
        need |= ((unsigned)(bx > 9.0f)) << (2 * p);
        need |= ((unsigned)(by > 9.0f)) << (2 * p + 1);
        float2 o;
        o.x = sqrt_approx(bx);
        o.y = sqrt_approx(by);
        *reinterpret_cast<float2*>(
            &out[(n * HH + i0 + lo0 + p) * WW + 2 * cp]) = o;
    }

    // exact tail, warp-uniform guard, ~never taken (needs d^2 > 9)
    if (__any_sync(0xFFFFFFFFu, need != 0u)) {
        #pragma unroll 1
        for (int e = 0; e < 8; ++e) if ((need >> e) & 1u) {
            const int p = e >> 1;
            const int j = 2 * cp + (e & 1);
            const int s = HALO + lo0 + p;      // this pixel's shared row
            const int i = i0 + lo0 + p;        // global row
            float best = fabsf(g2s[s][j]);     // center not NaN here (need set)
            best = fminf(best, 1.0f + fabsf(g2s[s - 1][j]));
            best = fminf(best, 1.0f + fabsf(g2s[s + 1][j]));
            best = fminf(best, 4.0f + fabsf(g2s[s - 2][j]));
            best = fminf(best, 4.0f + fabsf(g2s[s + 2][j]));
            // exact global recompute for r >= 3 (cold)
            for (int r = 3; r < HH; ++r) {
                const float r2 = (float)(r * r);
                if (r2 >= best) break;
                const int up = i - r, dn = i + r;
                if (up >= 0) {
                    const float g = row_g_global(x + (n * HH + up) * WW, j);
                    best = fminf(best, r2 + g * g);
                }
                if (dn < HH) {
                    const float g = row_g_global(x + (n * HH + dn) * WW, j);
                    best = fminf(best, r2 + g * g);
                }
            }
            out[(n * HH + i) * WW + j] = sqrt_approx(best);
        }
    }
}

extern "C" void kernel_launch(void* const* d_in, const int* in_sizes, int n_in,
                              void* d_out, int out_size) {
    const float* x = (const float*)d_in[0];
    float* out = (float*)d_out;
    edt_fused<<<dim3(HH / TILE, BN), 512>>>(x, out);
}